// round 15
// baseline (speedup 1.0000x reference)
#include <cuda_runtime.h>
#include <cstdint>

#define NPROP   2048
#define MAXN    256
#define D1      64
#define D2      128
#define D3      256
#define MIN_PTS 4
#define EPS     1e-6f
#define CHUNK   128

// ---- smem layout (float offsets) ----
// Interleaved-pair layout over a 128-point chunk: k-rows (k, k+4) adjacent so a
// B-fragment (b0=row k, b1=row k+4) is ONE float2 LDS.
// pair-row g = (k>>3)*4 + (k&3), half = (k>>2)&1, addr = g*PSTRIDE + col*2 + half.
// PSTRIDE = 2*128 + 8 -> stride mod 32 banks = 8: quad pattern (tid4,gid) hits
// banks tid4*8 + gid*2 + {0,1} = all 32 distinct per half-warp.
#define PSTRIDE  264
#define OFF_FE   0                              // 256 pooled feats
#define OFF_H1T  256                            // 32 pair-rows (k=64)
#define OFF_H2T  (256 + 32 * PSTRIDE)           // 64 pair-rows (k=128)
#define SMEM_FLOATS (OFF_H2T + 64 * PSTRIDE)    // 25600
#define SMEM_BYTES  (SMEM_FLOATS * 4)           // 102,400 B -> 2 CTAs/SM

// round fp32 -> nearest tf32-representable value (bits / float)
__device__ __forceinline__ uint32_t f32_to_tf32_bits(float x) {
    uint32_t r;
    asm("cvt.rna.tf32.f32 %0, %1;" : "=r"(r) : "f"(x));
    return r;
}
__device__ __forceinline__ float f32_to_tf32_f(float x) {
    return __uint_as_float(f32_to_tf32_bits(x));
}

// D(16x8) += A(16x8,row) * B(8x8,col), tf32 in, f32 accum (sm_80+ baseline PTX).
#define MMA_TF32(c, a, b0, b1) \
    asm volatile("mma.sync.aligned.m16n8k8.row.col.f32.tf32.tf32.f32 " \
        "{%0,%1,%2,%3}, {%4,%5,%6,%7}, {%8,%9}, {%0,%1,%2,%3};" \
        : "+f"((c)[0]), "+f"((c)[1]), "+f"((c)[2]), "+f"((c)[3]) \
        : "r"((a)[0]), "r"((a)[1]), "r"((a)[2]), "r"((a)[3]), \
          "r"(b0), "r"(b1))

__global__ __launch_bounds__(256, 2)
void refine_head_kernel(const float* __restrict__ points,
                        const int*   __restrict__ counts,
                        const float* __restrict__ proposals,
                        const float* __restrict__ W1, const float* __restrict__ b1,
                        const float* __restrict__ W2, const float* __restrict__ b2,
                        const float* __restrict__ W3, const float* __restrict__ b3,
                        const float* __restrict__ Wc, const float* __restrict__ bc,
                        const float* __restrict__ Wr, const float* __restrict__ br,
                        float* __restrict__ out)
{
    extern __shared__ float sm[];
    const int b    = blockIdx.x;
    const int tid  = threadIdx.x;
    const int wid  = tid >> 5;
    const int lane = tid & 31;
    const int tid4 = lane & 3;
    const int gid  = lane >> 2;
    const int n    = counts[b];

    // Invalid proposal: outputs are pure biases (uniform early-out).
    if (n < MIN_PTS) {
        if (tid == 0) out[b] = bc[0];
        if (tid < 6)  out[NPROP + b * 6 + tid] = br[tid];
        return;
    }

    // L3 running max, [mt*2 + rowhalf]; persists across point-chunks.
    float mx[4] = {-3.402823466e38f, -3.402823466e38f,
                   -3.402823466e38f, -3.402823466e38f};

    const int npc = (n + CHUNK - 1) >> 7;   // 1 or 2 point-chunks

    for (int pc = 0; pc < npc; pc++) {
        const int pbase = pc << 7;
        const int cn    = min(CHUNK, n - pbase);
        const int c16   = (cn + 15) >> 4;

        // ---- Phase 0: thread = point in chunk (only the first n unique points
        // matter — the reference's arange(256)%n gather merely duplicates points
        // and max-pool is duplicate-invariant). Layer 1 -> h1t pairs, tf32. ----
        if (tid < cn) {
            const float* pp = points + ((long)b * MAXN + pbase + tid) * 3;
            const float* pr = proposals + b * 6;
            const float c0 = (pp[0] - pr[0]) / (fabsf(pr[3]) + EPS);
            const float c1 = (pp[1] - pr[1]) / (fabsf(pr[4]) + EPS);
            const float c2 = (pp[2] - pr[2]) / (fabsf(pr[5]) + EPS);

            #pragma unroll
            for (int s = 0; s < 8; s++) {
                float h[8];
                #pragma unroll
                for (int hf = 0; hf < 2; hf++) {
                    float4 a = __ldg((const float4*)(W1)       + s * 2 + hf);
                    float4 d = __ldg((const float4*)(W1 + 64)  + s * 2 + hf);
                    float4 e = __ldg((const float4*)(W1 + 128) + s * 2 + hf);
                    float4 f = __ldg((const float4*)(b1)       + s * 2 + hf);
                    h[hf*4+0] = fmaxf(fmaf(c0, a.x, fmaf(c1, d.x, fmaf(c2, e.x, f.x))), 0.f);
                    h[hf*4+1] = fmaxf(fmaf(c0, a.y, fmaf(c1, d.y, fmaf(c2, e.y, f.y))), 0.f);
                    h[hf*4+2] = fmaxf(fmaf(c0, a.z, fmaf(c1, d.z, fmaf(c2, e.z, f.z))), 0.f);
                    h[hf*4+3] = fmaxf(fmaf(c0, a.w, fmaf(c1, d.w, fmaf(c2, e.w, f.w))), 0.f);
                }
                // store pairs (k = s*8+t, k+4) as one float2
                #pragma unroll
                for (int t = 0; t < 4; t++) {
                    float2 v;
                    v.x = f32_to_tf32_f(h[t]);
                    v.y = f32_to_tf32_f(h[t + 4]);
                    *(float2*)&sm[OFF_H1T + (s * 4 + t) * PSTRIDE + tid * 2] = v;
                }
            }
        }
        __syncthreads();

        // ---- Layer 2 on tensor cores: D[ch][pt] = W2T @ h1t.  Warp w owns the
        // m16 channel tile [w*16, w*16+16).  Output -> h2t pair layout. ----
        {
            const int chb = wid * 16;

            uint32_t A2[8][4];
            #pragma unroll
            for (int s = 0; s < 8; s++) {
                const int j0 = s * 8 + tid4;
                A2[s][0] = f32_to_tf32_bits(__ldg(W2 + j0 * D2 + chb + gid));
                A2[s][1] = f32_to_tf32_bits(__ldg(W2 + j0 * D2 + chb + gid + 8));
                A2[s][2] = f32_to_tf32_bits(__ldg(W2 + (j0 + 4) * D2 + chb + gid));
                A2[s][3] = f32_to_tf32_bits(__ldg(W2 + (j0 + 4) * D2 + chb + gid + 8));
            }
            const float b2v0 = __ldg(b2 + chb + gid);
            const float b2v1 = __ldg(b2 + chb + gid + 8);

            // epilogue store geometry (pair layout) for channels j0=chb+gid, j1=j0+8
            const int g0 = 8 * wid + (gid & 3);
            const int g1 = g0 + 4;
            const int h0 = (gid >> 2) & 1;

            for (int ck = 0; ck < c16; ck++) {
                const int colb = ck * 16;
                float c2f[2][4];
                #pragma unroll
                for (int nt = 0; nt < 2; nt++)
                    #pragma unroll
                    for (int q = 0; q < 4; q++) c2f[nt][q] = 0.f;

                #pragma unroll
                for (int s = 0; s < 8; s++) {
                    const float* base = &sm[OFF_H1T + (s * 4 + tid4) * PSTRIDE];
                    float2 p0 = *(const float2*)&base[(colb + gid) * 2];
                    float2 p1 = *(const float2*)&base[(colb + 8 + gid) * 2];
                    MMA_TF32(c2f[0], A2[s], __float_as_uint(p0.x), __float_as_uint(p0.y));
                    MMA_TF32(c2f[1], A2[s], __float_as_uint(p1.x), __float_as_uint(p1.y));
                }

                // epilogue: relu + bias, tf32-round, store into h2t pair layout
                #pragma unroll
                for (int nt = 0; nt < 2; nt++) {
                    const int col0 = colb + nt * 8 + 2 * tid4;
                    sm[OFF_H2T + g0 * PSTRIDE + col0 * 2 + h0] =
                        f32_to_tf32_f(fmaxf(c2f[nt][0] + b2v0, 0.f));
                    sm[OFF_H2T + g0 * PSTRIDE + (col0 + 1) * 2 + h0] =
                        f32_to_tf32_f(fmaxf(c2f[nt][1] + b2v0, 0.f));
                    sm[OFF_H2T + g1 * PSTRIDE + col0 * 2 + h0] =
                        f32_to_tf32_f(fmaxf(c2f[nt][2] + b2v1, 0.f));
                    sm[OFF_H2T + g1 * PSTRIDE + (col0 + 1) * 2 + h0] =
                        f32_to_tf32_f(fmaxf(c2f[nt][3] + b2v1, 0.f));
                }
            }
        }
        __syncthreads();

        // ---- Layer 3 + max-pool on tensor cores.  Warp w owns channels
        // [w*32, w*32+32); mt-outer keeps only a 64-reg A tile live (<=128 regs). ----
        {
            const int chb = wid * 32;

            #pragma unroll
            for (int mt = 0; mt < 2; mt++) {
                const int ch = chb + mt * 16 + gid;
                uint32_t A[16][4];
                #pragma unroll
                for (int s = 0; s < 16; s++) {
                    const int j0 = s * 8 + tid4;
                    A[s][0] = f32_to_tf32_bits(__ldg(W3 + j0 * D3 + ch));
                    A[s][1] = f32_to_tf32_bits(__ldg(W3 + j0 * D3 + ch + 8));
                    A[s][2] = f32_to_tf32_bits(__ldg(W3 + (j0 + 4) * D3 + ch));
                    A[s][3] = f32_to_tf32_bits(__ldg(W3 + (j0 + 4) * D3 + ch + 8));
                }

                for (int ck = 0; ck < c16; ck++) {
                    const int colb = ck * 16;
                    float c[2][4];
                    #pragma unroll
                    for (int nt = 0; nt < 2; nt++)
                        #pragma unroll
                        for (int q = 0; q < 4; q++) c[nt][q] = 0.f;

                    #pragma unroll
                    for (int s = 0; s < 16; s++) {
                        const float* base = &sm[OFF_H2T + (s * 4 + tid4) * PSTRIDE];
                        float2 p0 = *(const float2*)&base[(colb + gid) * 2];
                        float2 p1 = *(const float2*)&base[(colb + 8 + gid) * 2];
                        MMA_TF32(c[0], A[s], __float_as_uint(p0.x), __float_as_uint(p0.y));
                        MMA_TF32(c[1], A[s], __float_as_uint(p1.x), __float_as_uint(p1.y));
                    }

                    // fold into running per-row max (mask by GLOBAL point index)
                    #pragma unroll
                    for (int nt = 0; nt < 2; nt++) {
                        const int col0 = pbase + colb + nt * 8 + 2 * tid4;
                        if (col0 < n) {
                            mx[mt*2+0] = fmaxf(mx[mt*2+0], c[nt][0]);
                            mx[mt*2+1] = fmaxf(mx[mt*2+1], c[nt][2]);
                        }
                        if (col0 + 1 < n) {
                            mx[mt*2+0] = fmaxf(mx[mt*2+0], c[nt][1]);
                            mx[mt*2+1] = fmaxf(mx[mt*2+1], c[nt][3]);
                        }
                    }
                }
            }
        }
        __syncthreads();   // protect h1t/h2t before next chunk overwrites
    }

    // ---- Pool finish: quad-lane max union, + b3 -> feats in smem ----
    {
        #pragma unroll
        for (int o = 1; o < 4; o <<= 1) {
            #pragma unroll
            for (int q = 0; q < 4; q++)
                mx[q] = fmaxf(mx[q], __shfl_xor_sync(0xffffffffu, mx[q], o));
        }
        if (tid4 == 0) {
            #pragma unroll
            for (int mt = 0; mt < 2; mt++)
                #pragma unroll
                for (int rh = 0; rh < 2; rh++) {
                    const int ch = wid * 32 + mt * 16 + rh * 8 + gid;
                    sm[OFF_FE + ch] = mx[mt*2+rh] + __ldg(b3 + ch);
                }
        }
    }
    __syncthreads();

    // ---- Heads: 7 warps, each one dot(feats, column) + bias ----
    {
        if (wid < 7) {
            float s = 0.f;
            if (wid == 0) {
                #pragma unroll
                for (int k = lane; k < D3; k += 32) s += sm[OFF_FE + k] * __ldg(Wc + k);
            } else {
                const int r = wid - 1;
                #pragma unroll
                for (int k = lane; k < D3; k += 32) s += sm[OFF_FE + k] * __ldg(Wr + k * 6 + r);
            }
            #pragma unroll
            for (int off = 16; off > 0; off >>= 1)
                s += __shfl_down_sync(0xffffffffu, s, off);
            if (lane == 0) {
                if (wid == 0) out[b] = s + bc[0];
                else          out[NPROP + b * 6 + (wid - 1)] = s + br[wid - 1];
            }
        }
    }
}

extern "C" void kernel_launch(void* const* d_in, const int* in_sizes, int n_in,
                              void* d_out, int out_size)
{
    const float* points    = (const float*)d_in[0];
    const int*   counts    = (const int*)  d_in[1];
    const float* proposals = (const float*)d_in[2];
    const float* W1 = (const float*)d_in[3];
    const float* b1 = (const float*)d_in[4];
    const float* W2 = (const float*)d_in[5];
    const float* b2 = (const float*)d_in[6];
    const float* W3 = (const float*)d_in[7];
    const float* b3 = (const float*)d_in[8];
    const float* Wc = (const float*)d_in[9];
    const float* bc = (const float*)d_in[10];
    const float* Wr = (const float*)d_in[11];
    const float* br = (const float*)d_in[12];
    float* out = (float*)d_out;

    cudaFuncSetAttribute(refine_head_kernel,
                         cudaFuncAttributeMaxDynamicSharedMemorySize, SMEM_BYTES);
    refine_head_kernel<<<NPROP, 256, SMEM_BYTES>>>(
        points, counts, proposals, W1, b1, W2, b2, W3, b3, Wc, bc, Wr, br, out);
}

// round 16
// speedup vs baseline: 1.3398x; 1.3398x over previous
#include <cuda_runtime.h>
#include <cuda_fp16.h>
#include <cstdint>

#define NPROP   2048
#define MAXN    256
#define D1      64
#define D2      128
#define D3      256
#define MIN_PTS 4
#define EPS     1e-6f

// ---- smem layout (float offsets) ----
// f16 quad-entry layout: entry (g, col) is 8 bytes =
//   { half2(v[k], v[k+1]), half2(v[k+8], v[k+9]) },  k = 16*(g>>2) + 2*(g&3)
// which is exactly one m16n8k16 B-fragment (b0,b1) for lane (tid4=g&3) at
// k-block s=g>>2, column col.  GS = 2*256+8 floats; GS mod 32 = 8 ->
// quad read pattern hits banks tid4*8+gid*2+{0,1} = all distinct.
#define GS       520
#define OFF_FE   0                        // 256 pooled feats
#define OFF_RED  256                      // 8-wide max-reduction scratch
#define OFF_H1T  272                      // 16 entry-rows (K=64)
#define OFF_H2T  (272 + 16 * GS)          // 32 entry-rows (K=128)
#define SMEM_FLOATS (OFF_H2T + 32 * GS)   // 25232
#define SMEM_BYTES  (SMEM_FLOATS * 4)     // 100,928 B

__device__ __forceinline__ uint32_t pack_h2(float a, float b) {
    __half2 h = __floats2half2_rn(a, b);   // .x = a (low), .y = b (high)
    return *(uint32_t*)&h;
}

// D(16x8) += A(16x16,row) * B(16x8,col), f16 in, f32 accum (sm_80+ baseline).
#define MMA_F16(c, a, b0, b1) \
    asm volatile("mma.sync.aligned.m16n8k16.row.col.f32.f16.f16.f32 " \
        "{%0,%1,%2,%3}, {%4,%5,%6,%7}, {%8,%9}, {%0,%1,%2,%3};" \
        : "+f"((c)[0]), "+f"((c)[1]), "+f"((c)[2]), "+f"((c)[3]) \
        : "r"((a)[0]), "r"((a)[1]), "r"((a)[2]), "r"((a)[3]), \
          "r"(b0), "r"(b1))

__global__ __launch_bounds__(256, 1)
void refine_head_kernel(const float* __restrict__ points,
                        const int*   __restrict__ counts,
                        const float* __restrict__ proposals,
                        const float* __restrict__ W1, const float* __restrict__ b1,
                        const float* __restrict__ W2, const float* __restrict__ b2,
                        const float* __restrict__ W3, const float* __restrict__ b3,
                        const float* __restrict__ Wc, const float* __restrict__ bc,
                        const float* __restrict__ Wr, const float* __restrict__ br,
                        float* __restrict__ out)
{
    extern __shared__ float sm[];
    const int b    = blockIdx.x;
    const int tid  = threadIdx.x;
    const int wid  = tid >> 5;
    const int lane = tid & 31;
    const int tid4 = lane & 3;
    const int gid  = lane >> 2;
    const int n    = counts[b];

    // Invalid proposal: outputs are pure biases (uniform early-out).
    if (n < MIN_PTS) {
        if (tid == 0) out[b] = bc[0];
        if (tid < 6)  out[NPROP + b * 6 + tid] = br[tid];
        return;
    }

    // ---- Phase 0a: canon for every thread (reads are in-bounds up to MAXN;
    // only tid<n contributes), block-max -> per-proposal power-of-2 scale σ.
    // relu(σx)=σ relu(x) and biases scale linearly, so σ propagates exactly;
    // pooled maxes get multiplied by 1/σ (exact) at the end.  Keeps fp16
    // activations O(1..100), far from the 65504 ceiling. ----
    float c0, c1, c2;
    {
        const float* pp = points + ((long)b * MAXN + tid) * 3;
        const float* pr = proposals + b * 6;
        c0 = (pp[0] - pr[0]) / (fabsf(pr[3]) + EPS);
        c1 = (pp[1] - pr[1]) / (fabsf(pr[4]) + EPS);
        c2 = (pp[2] - pr[2]) / (fabsf(pr[5]) + EPS);
    }
    float m = 0.f;
    if (tid < n) m = fmaxf(fmaxf(fabsf(c0), fabsf(c1)), fabsf(c2));
    #pragma unroll
    for (int o = 16; o > 0; o >>= 1)
        m = fmaxf(m, __shfl_xor_sync(0xffffffffu, m, o));
    if (lane == 0) sm[OFF_RED + wid] = m;
    __syncthreads();
    float maxc = sm[OFF_RED + 0];
    #pragma unroll
    for (int w = 1; w < 8; w++) maxc = fmaxf(maxc, sm[OFF_RED + w]);
    const float e_exp     = rintf(log2f(maxc + 1e-30f));
    const float sigma     = exp2f(-e_exp);
    const float inv_sigma = exp2f(e_exp);

    // ---- Phase 0b: thread = point (only the first n unique points matter —
    // the reference's arange(256)%n gather merely duplicates points and
    // max-pool is duplicate-invariant). Layer 1 -> σ·h1 in f16 quad entries. ----
    if (tid < n) {
        #pragma unroll
        for (int s = 0; s < 4; s++) {
            float h[16];
            #pragma unroll
            for (int qq = 0; qq < 4; qq++) {
                float4 a = __ldg((const float4*)(W1)       + s * 4 + qq);
                float4 d = __ldg((const float4*)(W1 + 64)  + s * 4 + qq);
                float4 e = __ldg((const float4*)(W1 + 128) + s * 4 + qq);
                float4 f = __ldg((const float4*)(b1)       + s * 4 + qq);
                h[qq*4+0] = fmaxf(fmaf(c0, a.x, fmaf(c1, d.x, fmaf(c2, e.x, f.x))), 0.f) * sigma;
                h[qq*4+1] = fmaxf(fmaf(c0, a.y, fmaf(c1, d.y, fmaf(c2, e.y, f.y))), 0.f) * sigma;
                h[qq*4+2] = fmaxf(fmaf(c0, a.z, fmaf(c1, d.z, fmaf(c2, e.z, f.z))), 0.f) * sigma;
                h[qq*4+3] = fmaxf(fmaf(c0, a.w, fmaf(c1, d.w, fmaf(c2, e.w, f.w))), 0.f) * sigma;
            }
            #pragma unroll
            for (int t = 0; t < 4; t++) {
                float2 v;
                v.x = __uint_as_float(pack_h2(h[2*t],     h[2*t + 1]));
                v.y = __uint_as_float(pack_h2(h[2*t + 8], h[2*t + 9]));
                *(float2*)&sm[OFF_H1T + (4*s + t) * GS + tid * 2] = v;
            }
        }
    }
    __syncthreads();

    const int c16 = (n + 15) >> 4;

    // ---- Layer 2 (f16 MMA, K=64 -> 4 k16-steps): D = W2T @ (σ h1).
    // Warp w owns m16 channel tile [16w,16w+16).  Epilogue: +σb2, relu,
    // f16, paired via shfl into h2t quad entries. ----
    {
        const int chb = wid * 16;
        const int ch  = chb + gid;

        uint32_t A2[4][4];
        #pragma unroll
        for (int s = 0; s < 4; s++) {
            const int k0 = 16*s + 2*tid4;
            A2[s][0] = pack_h2(__ldg(W2 +  k0      * D2 + ch),     __ldg(W2 + (k0 + 1) * D2 + ch));
            A2[s][1] = pack_h2(__ldg(W2 +  k0      * D2 + ch + 8), __ldg(W2 + (k0 + 1) * D2 + ch + 8));
            A2[s][2] = pack_h2(__ldg(W2 + (k0 + 8) * D2 + ch),     __ldg(W2 + (k0 + 9) * D2 + ch));
            A2[s][3] = pack_h2(__ldg(W2 + (k0 + 8) * D2 + ch + 8), __ldg(W2 + (k0 + 9) * D2 + ch + 8));
        }
        const float sb2v0 = __ldg(b2 + ch)     * sigma;
        const float sb2v1 = __ldg(b2 + ch + 8) * sigma;

        const int u  = gid >> 1;            // entry row within warp (even gid)
        const int g2 = 4 * wid + u;

        for (int ck = 0; ck < c16; ck++) {
            const int colb = ck * 16;
            float cf[2][4];
            #pragma unroll
            for (int nt = 0; nt < 2; nt++)
                #pragma unroll
                for (int q = 0; q < 4; q++) cf[nt][q] = 0.f;

            #pragma unroll
            for (int s = 0; s < 4; s++) {
                const float* base = &sm[OFF_H1T + (4*s + tid4) * GS];
                float2 p0 = *(const float2*)&base[(colb + gid) * 2];
                float2 p1 = *(const float2*)&base[(colb + 8 + gid) * 2];
                MMA_F16(cf[0], A2[s], __float_as_uint(p0.x), __float_as_uint(p0.y));
                MMA_F16(cf[1], A2[s], __float_as_uint(p1.x), __float_as_uint(p1.y));
            }

            #pragma unroll
            for (int nt = 0; nt < 2; nt++) {
                const int col0 = colb + nt * 8 + 2 * tid4;
                float v0 = fmaxf(cf[nt][0] + sb2v0, 0.f);  // (ch,   col0)
                float v1 = fmaxf(cf[nt][1] + sb2v0, 0.f);  // (ch,   col0+1)
                float v2 = fmaxf(cf[nt][2] + sb2v1, 0.f);  // (ch+8, col0)
                float v3 = fmaxf(cf[nt][3] + sb2v1, 0.f);  // (ch+8, col0+1)
                // partner lane (gid^1) holds channel ch+1 / ch+9
                float p0 = __shfl_xor_sync(0xffffffffu, v0, 4);
                float p1 = __shfl_xor_sync(0xffffffffu, v1, 4);
                float p2 = __shfl_xor_sync(0xffffffffu, v2, 4);
                float p3 = __shfl_xor_sync(0xffffffffu, v3, 4);
                if ((gid & 1) == 0) {
                    float2 e0, e1;
                    e0.x = __uint_as_float(pack_h2(v0, p0));
                    e0.y = __uint_as_float(pack_h2(v2, p2));
                    e1.x = __uint_as_float(pack_h2(v1, p1));
                    e1.y = __uint_as_float(pack_h2(v3, p3));
                    *(float2*)&sm[OFF_H2T + g2 * GS + col0 * 2]       = e0;
                    *(float2*)&sm[OFF_H2T + g2 * GS + (col0 + 1) * 2] = e1;
                }
            }
        }
    }
    __syncthreads();

    // ---- Layer 3 + max-pool (f16 MMA, K=128 -> 8 k16-steps).  Warp w owns
    // channels [32w,32w+32): 2 m16 tiles sharing each B-fragment. ----
    const int chb3 = wid * 32;
    float mx[4] = {-3.402823466e38f, -3.402823466e38f,
                   -3.402823466e38f, -3.402823466e38f};   // [mt*2 + rowhalf]
    {
        uint32_t A3[8][2][4];
        #pragma unroll
        for (int s = 0; s < 8; s++) {
            const int k0 = 16*s + 2*tid4;
            #pragma unroll
            for (int mt = 0; mt < 2; mt++) {
                const int ch = chb3 + mt * 16 + gid;
                A3[s][mt][0] = pack_h2(__ldg(W3 +  k0      * D3 + ch),     __ldg(W3 + (k0 + 1) * D3 + ch));
                A3[s][mt][1] = pack_h2(__ldg(W3 +  k0      * D3 + ch + 8), __ldg(W3 + (k0 + 1) * D3 + ch + 8));
                A3[s][mt][2] = pack_h2(__ldg(W3 + (k0 + 8) * D3 + ch),     __ldg(W3 + (k0 + 9) * D3 + ch));
                A3[s][mt][3] = pack_h2(__ldg(W3 + (k0 + 8) * D3 + ch + 8), __ldg(W3 + (k0 + 9) * D3 + ch + 8));
            }
        }

        for (int ck = 0; ck < c16; ck++) {
            const int colb = ck * 16;
            float c[2][2][4];
            #pragma unroll
            for (int mt = 0; mt < 2; mt++)
                #pragma unroll
                for (int nt = 0; nt < 2; nt++)
                    #pragma unroll
                    for (int q = 0; q < 4; q++) c[mt][nt][q] = 0.f;

            #pragma unroll
            for (int s = 0; s < 8; s++) {
                const float* base = &sm[OFF_H2T + (4*s + tid4) * GS];
                float2 p0 = *(const float2*)&base[(colb + gid) * 2];
                float2 p1 = *(const float2*)&base[(colb + 8 + gid) * 2];
                const uint32_t b00 = __float_as_uint(p0.x), b01 = __float_as_uint(p0.y);
                const uint32_t b10 = __float_as_uint(p1.x), b11 = __float_as_uint(p1.y);
                MMA_F16(c[0][0], A3[s][0], b00, b01);
                MMA_F16(c[1][0], A3[s][1], b00, b01);
                MMA_F16(c[0][1], A3[s][0], b10, b11);
                MMA_F16(c[1][1], A3[s][1], b10, b11);
            }

            // fold into running per-row max (mask cols >= n)
            #pragma unroll
            for (int mt = 0; mt < 2; mt++) {
                #pragma unroll
                for (int nt = 0; nt < 2; nt++) {
                    const int col0 = colb + nt * 8 + 2 * tid4;
                    if (col0 < n) {
                        mx[mt*2+0] = fmaxf(mx[mt*2+0], c[mt][nt][0]);
                        mx[mt*2+1] = fmaxf(mx[mt*2+1], c[mt][nt][2]);
                    }
                    if (col0 + 1 < n) {
                        mx[mt*2+0] = fmaxf(mx[mt*2+0], c[mt][nt][1]);
                        mx[mt*2+1] = fmaxf(mx[mt*2+1], c[mt][nt][3]);
                    }
                }
            }
        }
    }

    // ---- Pool finish: quad-lane max union, de-scale (exact 2^e), +b3 ----
    {
        #pragma unroll
        for (int o = 1; o < 4; o <<= 1) {
            #pragma unroll
            for (int q = 0; q < 4; q++)
                mx[q] = fmaxf(mx[q], __shfl_xor_sync(0xffffffffu, mx[q], o));
        }
        if (tid4 == 0) {
            #pragma unroll
            for (int mt = 0; mt < 2; mt++)
                #pragma unroll
                for (int rh = 0; rh < 2; rh++) {
                    const int ch = chb3 + mt * 16 + rh * 8 + gid;
                    sm[OFF_FE + ch] = mx[mt*2+rh] * inv_sigma + __ldg(b3 + ch);
                }
        }
    }
    __syncthreads();

    // ---- Heads: 7 warps, each one dot(feats, column) + bias ----
    {
        if (wid < 7) {
            float s = 0.f;
            if (wid == 0) {
                #pragma unroll
                for (int k = lane; k < D3; k += 32) s += sm[OFF_FE + k] * __ldg(Wc + k);
            } else {
                const int r = wid - 1;
                #pragma unroll
                for (int k = lane; k < D3; k += 32) s += sm[OFF_FE + k] * __ldg(Wr + k * 6 + r);
            }
            #pragma unroll
            for (int off = 16; off > 0; off >>= 1)
                s += __shfl_down_sync(0xffffffffu, s, off);
            if (lane == 0) {
                if (wid == 0) out[b] = s + bc[0];
                else          out[NPROP + b * 6 + (wid - 1)] = s + br[wid - 1];
            }
        }
    }
}

extern "C" void kernel_launch(void* const* d_in, const int* in_sizes, int n_in,
                              void* d_out, int out_size)
{
    const float* points    = (const float*)d_in[0];
    const int*   counts    = (const int*)  d_in[1];
    const float* proposals = (const float*)d_in[2];
    const float* W1 = (const float*)d_in[3];
    const float* b1 = (const float*)d_in[4];
    const float* W2 = (const float*)d_in[5];
    const float* b2 = (const float*)d_in[6];
    const float* W3 = (const float*)d_in[7];
    const float* b3 = (const float*)d_in[8];
    const float* Wc = (const float*)d_in[9];
    const float* bc = (const float*)d_in[10];
    const float* Wr = (const float*)d_in[11];
    const float* br = (const float*)d_in[12];
    float* out = (float*)d_out;

    cudaFuncSetAttribute(refine_head_kernel,
                         cudaFuncAttributeMaxDynamicSharedMemorySize, SMEM_BYTES);
    refine_head_kernel<<<NPROP, 256, SMEM_BYTES>>>(
        points, counts, proposals, W1, b1, W2, b2, W3, b3, Wc, bc, Wr, br, out);
}